// round 2
// baseline (speedup 1.0000x reference)
#include <cuda_runtime.h>
#include <cuda_bf16.h>

#define NQ 2048
#define NB 8192
#define DIM 32
#define JSPLIT 8          // blocks along j
#define QT 64             // queries per block (8 warps x 8 q)
#define JT 256            // background points per smem tile
#define JRANGE (NB / JSPLIT)      // 1024 per block
#define NTILES (JRANGE / JT)      // 4

// ---------------- device scratch (no allocs allowed) ----------------
__device__ float g_xbwT[DIM * NB];    // [k][j]  (x_backgnd * w, transposed)
__device__ float g_b2[NB];
__device__ float g_xqw[NQ * DIM];     // [q][k]  (x_query * w)
__device__ float g_q2[NQ];
__device__ float g_part[JSPLIT * NQ * 2];   // per-jsplit partial (ksum, kysum)

// ---------------- f32x2 helpers (Blackwell packed fp32) ----------------
#define FMA2(d, a, b, c) asm("fma.rn.f32x2 %0, %1, %2, %3;" : "=l"(d) : "l"(a), "l"(b), "l"(c))
#define ADD2(d, a, b)    asm("add.rn.f32x2 %0, %1, %2;"     : "=l"(d) : "l"(a), "l"(b))
#define MUL2(d, a, b)    asm("mul.rn.f32x2 %0, %1, %2;"     : "=l"(d) : "l"(a), "l"(b))
#define PACK2(d, lo, hi) asm("mov.b64 %0, {%1, %2};" : "=l"(d) : "f"(lo), "f"(hi))
#define UNPACK2(lo, hi, v) asm("mov.b64 {%0, %1}, %2;" : "=f"(lo), "=f"(hi) : "l"(v))
#define SQRTA(d, x)      asm("sqrt.approx.ftz.f32 %0, %1;" : "=f"(d) : "f"(x))
#define EX2A(d, x)       asm("ex2.approx.ftz.f32 %0, %1;"  : "=f"(d) : "f"(x))

// ---------------- prep kernels ----------------
__global__ void prep_xbw(const float* __restrict__ xb, const float* __restrict__ w) {
    int idx = blockIdx.x * blockDim.x + threadIdx.x;
    if (idx < NB * DIM) {
        int j = idx & (NB - 1);
        int k = idx >> 13;                 // idx / NB
        g_xbwT[idx] = xb[j * DIM + k] * w[k];
    }
}

__global__ void prep_xqw(const float* __restrict__ xq, const float* __restrict__ w) {
    int idx = blockIdx.x * blockDim.x + threadIdx.x;
    if (idx < NQ * DIM) {
        g_xqw[idx] = xq[idx] * w[idx & (DIM - 1)];
    }
}

__global__ void prep_sq() {
    int i = blockIdx.x * blockDim.x + threadIdx.x;
    if (i < NB) {
        float s = 0.f;
        #pragma unroll
        for (int k = 0; k < DIM; ++k) {
            float v = g_xbwT[k * NB + i];
            s = fmaf(v, v, s);
        }
        g_b2[i] = s;
    } else if (i < NB + NQ) {
        int q = i - NB;
        float s = 0.f;
        #pragma unroll
        for (int k = 0; k < DIM; ++k) {
            float v = g_xqw[q * DIM + k];
            s = fmaf(v, v, s);
        }
        g_q2[q] = s;
    }
}

// ---------------- main kernel ----------------
// grid (32, JSPLIT), block 256. warp w handles queries [qbase + 8w, +8), lanes = j.
// Per-thread tile: 8 queries x 8 background points (4 f32x2 pairs).
__global__ __launch_bounds__(256) void nw_main(
    const float* __restrict__ yb,
    const float* __restrict__ r,
    const float* __restrict__ sigma,
    const float* __restrict__ r_scale)
{
    __shared__ __align__(16) float xb_s[DIM][JT];   // 32 KB, k-major, b contiguous
    __shared__ __align__(16) float xq_s[DIM][QT];   // 8 KB
    __shared__ __align__(16) float b2_s[JT];
    __shared__ __align__(16) float y_s[JT];

    const int tid   = threadIdx.x;
    const int lane  = tid & 31;
    const int warp  = tid >> 5;
    const int qbase = blockIdx.x * QT;
    const int jbase0 = blockIdx.y * JRANGE;

    // fill per-block query fragments
    for (int e = tid; e < QT * DIM; e += 256) {
        int q = e & (QT - 1);
        int k = e >> 6;
        xq_s[k][q] = g_xqw[(qbase + q) * DIM + k];
    }

    // constants (fold log2e into sigma / r_scale so exp -> single ex2)
    const float L2E = 1.4426950408889634f;
    const float cr = r_scale[0] * L2E;
    const float cd = -L2E / sigma[0];
    unsigned long long cr2, cd2, n22;
    PACK2(cr2, cr, cr);
    PACK2(cd2, cd, cd);
    PACK2(n22, -2.0f, -2.0f);

    float q2r[8];
    #pragma unroll
    for (int q = 0; q < 8; ++q) q2r[q] = g_q2[qbase + warp * 8 + q];

    float ksum[8], kysum[8];
    #pragma unroll
    for (int q = 0; q < 8; ++q) { ksum[q] = 0.f; kysum[q] = 0.f; }

    for (int t = 0; t < NTILES; ++t) {
        const int jb = jbase0 + t * JT;
        __syncthreads();   // previous tile fully consumed
        // stage xb tile (k-major), b2, y
        for (int e = tid; e < DIM * (JT / 4); e += 256) {
            int k = e >> 6;            // JT/4 = 64 float4 per row
            int c = e & 63;
            *(float4*)&xb_s[k][c * 4] = *(const float4*)&g_xbwT[k * NB + jb + c * 4];
        }
        if (tid < JT / 4) {
            *(float4*)&b2_s[tid * 4] = *(const float4*)&g_b2[jb + tid * 4];
        } else if (tid < JT / 2) {
            int u = tid - JT / 4;
            *(float4*)&y_s[u * 4] = *(const float4*)&yb[jb + u * 4];
        }
        __syncthreads();

        // -------- dot phase: acc[q][bi] = packed dot over k --------
        unsigned long long acc[8][4];
        #pragma unroll
        for (int q = 0; q < 8; ++q)
            #pragma unroll
            for (int bi = 0; bi < 4; ++bi) acc[q][bi] = 0ull;

        #pragma unroll 4
        for (int k = 0; k < DIM; ++k) {
            unsigned long long xb2[4];
            #pragma unroll
            for (int bi = 0; bi < 4; ++bi)
                xb2[bi] = *(const unsigned long long*)&xb_s[k][lane * 2 + 64 * bi];
            #pragma unroll
            for (int q = 0; q < 8; ++q) {
                float xv = xq_s[k][warp * 8 + q];   // broadcast LDS
                unsigned long long xq2;
                PACK2(xq2, xv, xv);
                #pragma unroll
                for (int bi = 0; bi < 4; ++bi)
                    FMA2(acc[q][bi], xq2, xb2[bi], acc[q][bi]);
            }
        }

        // -------- epilogue: dist, exp, accumulate --------
        unsigned long long b22[4], y22[4];
        #pragma unroll
        for (int bi = 0; bi < 4; ++bi) {
            b22[bi] = *(const unsigned long long*)&b2_s[lane * 2 + 64 * bi];
            y22[bi] = *(const unsigned long long*)&y_s[lane * 2 + 64 * bi];
        }

        #pragma unroll
        for (int q = 0; q < 8; ++q) {
            const float* rr = r + (qbase + warp * 8 + q) * NB + jb;
            unsigned long long q2d;
            PACK2(q2d, q2r[q], q2r[q]);
            unsigned long long kt = 0ull, kyt = 0ull;
            #pragma unroll
            for (int bi = 0; bi < 4; ++bi) {
                float2 rv = *(const float2*)&rr[lane * 2 + 64 * bi];
                unsigned long long s2, d22, dd, rv2, rc, tt, kk;
                ADD2(s2, q2d, b22[bi]);
                FMA2(d22, acc[q][bi], n22, s2);     // d2 = q2+b2 - 2*dot
                float dl, dh;
                UNPACK2(dl, dh, d22);
                dl = fmaxf(dl, 0.f);
                dh = fmaxf(dh, 0.f);
                SQRTA(dl, dl);
                SQRTA(dh, dh);
                PACK2(dd, dl, dh);
                PACK2(rv2, rv.x, rv.y);
                MUL2(rc, rv2, cr2);                  // r * (r_scale*log2e)
                FMA2(tt, dd, cd2, rc);               // -dist*(log2e/sigma) + ...
                float tl, th, kl, kh;
                UNPACK2(tl, th, tt);
                EX2A(kl, tl);
                EX2A(kh, th);
                PACK2(kk, kl, kh);
                ADD2(kt, kt, kk);
                FMA2(kyt, kk, y22[bi], kyt);
            }
            float a, b;
            UNPACK2(a, b, kt);
            ksum[q] += a + b;
            UNPACK2(a, b, kyt);
            kysum[q] += a + b;
        }
    }

    // warp-level reduction over the 32 j-lanes, write per-jsplit partials
    #pragma unroll
    for (int q = 0; q < 8; ++q) {
        float ks = ksum[q];
        float ky = kysum[q];
        #pragma unroll
        for (int off = 16; off; off >>= 1) {
            ks += __shfl_xor_sync(0xffffffffu, ks, off);
            ky += __shfl_xor_sync(0xffffffffu, ky, off);
        }
        if (lane == 0) {
            int qg = qbase + warp * 8 + q;
            g_part[(blockIdx.y * NQ + qg) * 2 + 0] = ks;
            g_part[(blockIdx.y * NQ + qg) * 2 + 1] = ky;
        }
    }
}

// ---------------- final reduce over j-splits (deterministic) ----------------
__global__ void nw_reduce(float* __restrict__ out) {
    int i = blockIdx.x * blockDim.x + threadIdx.x;
    if (i < NQ) {
        float ks = 0.f, ky = 0.f;
        #pragma unroll
        for (int s = 0; s < JSPLIT; ++s) {
            ks += g_part[(s * NQ + i) * 2 + 0];
            ky += g_part[(s * NQ + i) * 2 + 1];
        }
        out[i] = ky / (ks + 1e-8f);
    }
}

// ---------------- launch ----------------
extern "C" void kernel_launch(void* const* d_in, const int* in_sizes, int n_in,
                              void* d_out, int out_size) {
    (void)in_sizes; (void)n_in; (void)out_size;
    const float* x_backgnd = (const float*)d_in[0];
    const float* y_backgnd = (const float*)d_in[1];
    const float* x_query   = (const float*)d_in[2];
    const float* r         = (const float*)d_in[3];
    const float* sigma     = (const float*)d_in[4];
    const float* r_scale   = (const float*)d_in[5];
    const float* w         = (const float*)d_in[6];
    float* out = (float*)d_out;

    prep_xbw<<<(NB * DIM + 255) / 256, 256>>>(x_backgnd, w);
    prep_xqw<<<(NQ * DIM + 255) / 256, 256>>>(x_query, w);
    prep_sq<<<(NB + NQ + 255) / 256, 256>>>();
    nw_main<<<dim3(NQ / QT, JSPLIT), 256>>>(y_backgnd, r, sigma, r_scale);
    nw_reduce<<<(NQ + 255) / 256, 256>>>(out);
}

// round 3
// speedup vs baseline: 1.1216x; 1.1216x over previous
#include <cuda_runtime.h>
#include <cuda_bf16.h>

#define NQ 2048
#define NB 8192
#define DIM 32
#define QT 64             // queries per block (8 warps x 8 q)
#define JT 256            // background points per block (single tile)
#define JSPLIT (NB / JT)  // 32 j-blocks

// ---------------- device scratch (no allocs allowed) ----------------
__device__ float g_xbwT[DIM * NB];          // [k][j]  (x_backgnd * w, transposed)
__device__ float g_b2[NB];
__device__ float g_xqw[NQ * DIM];           // [q][k]  (x_query * w)
__device__ float g_q2[NQ];
__device__ float g_part[NQ * JSPLIT * 2];   // [q][split]{ksum, kysum}

// ---------------- f32x2 helpers (Blackwell packed fp32) ----------------
#define FMA2(d, a, b, c) asm("fma.rn.f32x2 %0, %1, %2, %3;" : "=l"(d) : "l"(a), "l"(b), "l"(c))
#define ADD2(d, a, b)    asm("add.rn.f32x2 %0, %1, %2;"     : "=l"(d) : "l"(a), "l"(b))
#define MUL2(d, a, b)    asm("mul.rn.f32x2 %0, %1, %2;"     : "=l"(d) : "l"(a), "l"(b))
#define PACK2(d, lo, hi) asm("mov.b64 %0, {%1, %2};" : "=l"(d) : "f"(lo), "f"(hi))
#define UNPACK2(lo, hi, v) asm("mov.b64 {%0, %1}, %2;" : "=f"(lo), "=f"(hi) : "l"(v))
#define SQRTA(d, x)      asm("sqrt.approx.ftz.f32 %0, %1;" : "=f"(d) : "f"(x))
#define EX2A(d, x)       asm("ex2.approx.ftz.f32 %0, %1;"  : "=f"(d) : "f"(x))

// ---------------- fused prep: weight, transpose, squared norms ----------------
__global__ void prep_all(const float* __restrict__ xb, const float* __restrict__ xq,
                         const float* __restrict__ w) {
    int i = blockIdx.x * blockDim.x + threadIdx.x;
    if (i < NB) {
        float s = 0.f;
        #pragma unroll
        for (int c = 0; c < 8; ++c) {
            float4 t = *(const float4*)&xb[i * DIM + c * 4];
            t.x *= w[c * 4 + 0]; t.y *= w[c * 4 + 1];
            t.z *= w[c * 4 + 2]; t.w *= w[c * 4 + 3];
            g_xbwT[(c * 4 + 0) * NB + i] = t.x;
            g_xbwT[(c * 4 + 1) * NB + i] = t.y;
            g_xbwT[(c * 4 + 2) * NB + i] = t.z;
            g_xbwT[(c * 4 + 3) * NB + i] = t.w;
            s = fmaf(t.x, t.x, fmaf(t.y, t.y, fmaf(t.z, t.z, fmaf(t.w, t.w, s))));
        }
        g_b2[i] = s;
    } else if (i < NB + NQ) {
        int q = i - NB;
        float s = 0.f;
        #pragma unroll
        for (int c = 0; c < 8; ++c) {
            float4 t = *(const float4*)&xq[q * DIM + c * 4];
            t.x *= w[c * 4 + 0]; t.y *= w[c * 4 + 1];
            t.z *= w[c * 4 + 2]; t.w *= w[c * 4 + 3];
            *(float4*)&g_xqw[q * DIM + c * 4] = t;
            s = fmaf(t.x, t.x, fmaf(t.y, t.y, fmaf(t.z, t.z, fmaf(t.w, t.w, s))));
        }
        g_q2[q] = s;
    }
}

// ---------------- main kernel ----------------
// grid (NQ/QT=32, JSPLIT=32), block 256, 2 CTAs/SM target.
// warp w -> queries [qbase + 8w, +8); lanes tile j via LDS.128 quads:
// per-thread j indices = {lane*4 .. lane*4+3} and {+128}.
// xq lives in registers distributed over lanes (lane <-> k), fetched via shfl.
__global__ __launch_bounds__(256, 2) void nw_main(
    const float* __restrict__ yb,
    const float* __restrict__ r,
    const float* __restrict__ sigma,
    const float* __restrict__ r_scale)
{
    __shared__ __align__(16) float xb_s[DIM][JT];   // 32 KB, k-major
    __shared__ __align__(16) float b2_s[JT];
    __shared__ __align__(16) float y_s[JT];

    const int tid   = threadIdx.x;
    const int lane  = tid & 31;
    const int warp  = tid >> 5;
    const int qbase = blockIdx.x * QT;
    const int jb    = blockIdx.y * JT;
    const int qg0   = qbase + warp * 8;

    // stage xb tile (k-major), b2, y : 32 rows x 64 float4 = 2048 float4
    #pragma unroll
    for (int e = tid; e < DIM * (JT / 4); e += 256) {
        int k = e >> 6;
        int c = e & 63;
        *(float4*)&xb_s[k][c * 4] = *(const float4*)&g_xbwT[k * NB + jb + c * 4];
    }
    if (tid < JT / 4) {
        *(float4*)&b2_s[tid * 4] = *(const float4*)&g_b2[jb + tid * 4];
    } else if (tid < JT / 2) {
        int u = tid - JT / 4;
        *(float4*)&y_s[u * 4] = *(const float4*)&yb[jb + u * 4];
    }

    // xq for this warp's 8 queries, distributed over lanes (lane <-> k)
    float xr[8];
    #pragma unroll
    for (int q = 0; q < 8; ++q)
        xr[q] = g_xqw[(qg0 + q) * DIM + lane];

    __syncthreads();

    // -------- dot phase --------
    unsigned long long acc[8][4];
    #pragma unroll
    for (int q = 0; q < 8; ++q)
        #pragma unroll
        for (int bi = 0; bi < 4; ++bi) acc[q][bi] = 0ull;

    #pragma unroll 8
    for (int k = 0; k < DIM; ++k) {
        ulonglong2 B0 = *(const ulonglong2*)&xb_s[k][lane * 4];
        ulonglong2 B1 = *(const ulonglong2*)&xb_s[k][lane * 4 + 128];
        #pragma unroll
        for (int q = 0; q < 8; ++q) {
            float xv = __shfl_sync(0xffffffffu, xr[q], k);
            unsigned long long xq2;
            PACK2(xq2, xv, xv);
            FMA2(acc[q][0], xq2, B0.x, acc[q][0]);
            FMA2(acc[q][1], xq2, B0.y, acc[q][1]);
            FMA2(acc[q][2], xq2, B1.x, acc[q][2]);
            FMA2(acc[q][3], xq2, B1.y, acc[q][3]);
        }
    }

    // -------- epilogue: dist, exp, accumulate --------
    const float L2E = 1.4426950408889634f;
    const float crf = r_scale[0] * L2E;
    const float cdf = -L2E / sigma[0];
    unsigned long long cr2, cd2, n22;
    PACK2(cr2, crf, crf);
    PACK2(cd2, cdf, cdf);
    PACK2(n22, -2.0f, -2.0f);

    #pragma unroll
    for (int q = 0; q < 8; ++q) {
        const int qg = qg0 + q;
        float q2v = g_q2[qg];
        unsigned long long q2d;
        PACK2(q2d, q2v, q2v);
        const float* rr = r + (size_t)qg * NB + jb;
        unsigned long long kt = 0ull, kyt = 0ull;

        #pragma unroll
        for (int h = 0; h < 2; ++h) {
            const int joff = lane * 4 + 128 * h;
            ulonglong2 rv = *(const ulonglong2*)&rr[joff];
            ulonglong2 bb = *(const ulonglong2*)&b2_s[joff];
            ulonglong2 yy = *(const ulonglong2*)&y_s[joff];
            #pragma unroll
            for (int p = 0; p < 2; ++p) {
                unsigned long long a  = acc[q][h * 2 + p];
                unsigned long long bp = p ? bb.y : bb.x;
                unsigned long long yp = p ? yy.y : yy.x;
                unsigned long long rp = p ? rv.y : rv.x;
                unsigned long long s2, d22, dd, rc, tt, kk;
                ADD2(s2, q2d, bp);
                FMA2(d22, a, n22, s2);              // d2 = q2 + b2 - 2*dot
                float dl, dh;
                UNPACK2(dl, dh, d22);
                dl = fmaxf(dl, 0.f);
                dh = fmaxf(dh, 0.f);
                SQRTA(dl, dl);
                SQRTA(dh, dh);
                PACK2(dd, dl, dh);
                MUL2(rc, rp, cr2);                   // r * (r_scale*log2e)
                FMA2(tt, dd, cd2, rc);               // -dist*(log2e/sigma) + ...
                float tl, th, kl, kh;
                UNPACK2(tl, th, tt);
                EX2A(kl, tl);
                EX2A(kh, th);
                PACK2(kk, kl, kh);
                ADD2(kt, kt, kk);
                FMA2(kyt, kk, yp, kyt);
            }
        }

        float a0, a1, ks, ky;
        UNPACK2(a0, a1, kt);
        ks = a0 + a1;
        UNPACK2(a0, a1, kyt);
        ky = a0 + a1;
        #pragma unroll
        for (int off = 16; off; off >>= 1) {
            ks += __shfl_xor_sync(0xffffffffu, ks, off);
            ky += __shfl_xor_sync(0xffffffffu, ky, off);
        }
        if (lane == 0) {
            g_part[(qg * JSPLIT + blockIdx.y) * 2 + 0] = ks;
            g_part[(qg * JSPLIT + blockIdx.y) * 2 + 1] = ky;
        }
    }
}

// ---------------- final reduce over j-splits (deterministic) ----------------
__global__ void nw_reduce(float* __restrict__ out) {
    int q = blockIdx.x * blockDim.x + threadIdx.x;
    if (q < NQ) {
        float ks = 0.f, ky = 0.f;
        const float2* p = (const float2*)&g_part[q * JSPLIT * 2];
        #pragma unroll
        for (int s = 0; s < JSPLIT; ++s) {
            float2 v = p[s];
            ks += v.x;
            ky += v.y;
        }
        out[q] = ky / (ks + 1e-8f);
    }
}

// ---------------- launch ----------------
extern "C" void kernel_launch(void* const* d_in, const int* in_sizes, int n_in,
                              void* d_out, int out_size) {
    (void)in_sizes; (void)n_in; (void)out_size;
    const float* x_backgnd = (const float*)d_in[0];
    const float* y_backgnd = (const float*)d_in[1];
    const float* x_query   = (const float*)d_in[2];
    const float* r         = (const float*)d_in[3];
    const float* sigma     = (const float*)d_in[4];
    const float* r_scale   = (const float*)d_in[5];
    const float* w         = (const float*)d_in[6];
    float* out = (float*)d_out;

    prep_all<<<(NB + NQ + 255) / 256, 256>>>(x_backgnd, x_query, w);
    nw_main<<<dim3(NQ / QT, JSPLIT), 256>>>(y_backgnd, r, sigma, r_scale);
    nw_reduce<<<(NQ + 255) / 256, 256>>>(out);
}

// round 4
// speedup vs baseline: 1.1857x; 1.0572x over previous
#include <cuda_runtime.h>
#include <cuda_bf16.h>

#define NQ 2048
#define NB 8192
#define DIM 32
#define QT 64             // queries per block (8 warps x 8 q)
#define JT 256            // background points per block (single tile)
#define JSPLIT (NB / JT)  // 32 j-blocks

// ---------------- device scratch (no allocs allowed) ----------------
__device__ float g_xbwT[DIM * NB];          // [k][j]  (x_backgnd * w, transposed)
__device__ float g_xqw[NQ * DIM];           // [q][k]  (x_query * w)
__device__ float g_part[NQ * JSPLIT * 2];   // [q][split]{ksum, kysum}

// ---------------- f32x2 helpers (Blackwell packed fp32) ----------------
#define FMA2(d, a, b, c) asm("fma.rn.f32x2 %0, %1, %2, %3;" : "=l"(d) : "l"(a), "l"(b), "l"(c))
#define ADD2(d, a, b)    asm("add.rn.f32x2 %0, %1, %2;"     : "=l"(d) : "l"(a), "l"(b))
#define MUL2(d, a, b)    asm("mul.rn.f32x2 %0, %1, %2;"     : "=l"(d) : "l"(a), "l"(b))
#define PACK2(d, lo, hi) asm("mov.b64 %0, {%1, %2};" : "=l"(d) : "f"(lo), "f"(hi))
#define UNPACK2(lo, hi, v) asm("mov.b64 {%0, %1}, %2;" : "=f"(lo), "=f"(hi) : "l"(v))
#define SQRTA(d, x)      asm("sqrt.approx.ftz.f32 %0, %1;" : "=f"(d) : "f"(x))
#define EX2A(d, x)       asm("ex2.approx.ftz.f32 %0, %1;"  : "=f"(d) : "f"(x))

// cp.async helpers
#define CP16(dst, src)   asm volatile("cp.async.cg.shared.global [%0], [%1], 16;" :: "r"(dst), "l"(src))
#define CP_COMMIT()      asm volatile("cp.async.commit_group;")
#define CP_WAIT(n)       asm volatile("cp.async.wait_group %0;" :: "n"(n))

// ---------------- prep: weight-multiply + transpose (fine-grained) ----------------
// One float4 of one row per thread. 320 blocks, fully parallel.
__global__ void prep(const float* __restrict__ xb, const float* __restrict__ xq,
                     const float* __restrict__ w) {
    int idx = blockIdx.x * blockDim.x + threadIdx.x;
    if (idx < NB * 8) {
        int c = idx >> 13;            // / NB
        int i = idx & (NB - 1);
        float4 t = *(const float4*)&xb[i * DIM + c * 4];
        t.x *= w[c * 4 + 0]; t.y *= w[c * 4 + 1];
        t.z *= w[c * 4 + 2]; t.w *= w[c * 4 + 3];
        g_xbwT[(c * 4 + 0) * NB + i] = t.x;   // coalesced across lanes (i contiguous)
        g_xbwT[(c * 4 + 1) * NB + i] = t.y;
        g_xbwT[(c * 4 + 2) * NB + i] = t.z;
        g_xbwT[(c * 4 + 3) * NB + i] = t.w;
    } else {
        int e = idx - NB * 8;
        if (e < NQ * 8) {
            int q = e >> 3;
            int c = e & 7;
            float4 t = *(const float4*)&xq[q * DIM + c * 4];
            t.x *= w[c * 4 + 0]; t.y *= w[c * 4 + 1];
            t.z *= w[c * 4 + 2]; t.w *= w[c * 4 + 3];
            *(float4*)&g_xqw[q * DIM + c * 4] = t;
        }
    }
}

// ---------------- main kernel ----------------
// grid (NQ/QT=32, JSPLIT=32), block 256, 2 CTAs/SM.
// warp w -> queries [qbase + 8w, +8); per-thread j = {lane*4..+3} and {+128}.
// r tile (64 KB) prefetched via cp.async, overlapped with the dot phase.
__global__ __launch_bounds__(256, 2) void nw_main(
    const float* __restrict__ yb,
    const float* __restrict__ r,
    const float* __restrict__ sigma,
    const float* __restrict__ r_scale)
{
    extern __shared__ __align__(16) float smem[];
    float* xb_s = smem;                      // [DIM][JT]  32 KB
    float* r_s  = smem + DIM * JT;           // [QT][JT]   64 KB
    float* b2_s = r_s + QT * JT;             // [JT]
    float* y_s  = b2_s + JT;                 // [JT]

    const int tid   = threadIdx.x;
    const int lane  = tid & 31;
    const int warp  = tid >> 5;
    const int qbase = blockIdx.x * QT;
    const int jb    = blockIdx.y * JT;
    const int qg0   = qbase + warp * 8;

    unsigned int sbase;
    asm("{ .reg .u64 t; cvta.to.shared.u64 t, %1; cvt.u32.u64 %0, t; }" : "=r"(sbase) : "l"(smem));

    // ---- group A: xb tile (k-major) + y ----
    #pragma unroll
    for (int it = 0; it < 8; ++it) {
        int e = tid + 256 * it;              // 2048 chunks of 16B
        int k = e >> 6;
        int c = e & 63;
        CP16(sbase + (unsigned)((k * JT + c * 4) * 4),
             (const char*)&g_xbwT[k * NB + jb + c * 4]);
    }
    if (tid < JT / 4) {
        CP16(sbase + (unsigned)((DIM * JT + QT * JT + JT + tid * 4) * 4),
             (const char*)&yb[jb + tid * 4]);
    }
    CP_COMMIT();

    // ---- group B: r tile [QT][JT] ----
    #pragma unroll
    for (int it = 0; it < 16; ++it) {
        int e = tid + 256 * it;              // 4096 chunks of 16B
        int row = e >> 6;
        int col = e & 63;
        CP16(sbase + (unsigned)((DIM * JT + row * JT + col * 4) * 4),
             (const char*)&r[(size_t)(qbase + row) * NB + jb + col * 4]);
    }
    CP_COMMIT();

    // xq for this warp's 8 queries, distributed over lanes (lane <-> k); q2 via butterfly
    float xr[8], q2w[8];
    #pragma unroll
    for (int q = 0; q < 8; ++q)
        xr[q] = g_xqw[(qg0 + q) * DIM + lane];
    #pragma unroll
    for (int q = 0; q < 8; ++q) {
        float s = xr[q] * xr[q];
        #pragma unroll
        for (int off = 16; off; off >>= 1)
            s += __shfl_xor_sync(0xffffffffu, s, off);
        q2w[q] = s;
    }

    CP_WAIT(1);          // group A (xb, y) arrived; B still in flight
    __syncthreads();

    // b2 in-block: thread j = tid sums xb_s[k][j]^2 (conflict-free column reads)
    {
        float s = 0.f;
        #pragma unroll
        for (int k = 0; k < DIM; ++k) {
            float v = xb_s[k * JT + tid];
            s = fmaf(v, v, s);
        }
        b2_s[tid] = s;   // visibility guarded by the post-dot __syncthreads
    }

    // -------- dot phase (overlaps with group B DRAM traffic) --------
    unsigned long long acc[8][4];
    #pragma unroll
    for (int q = 0; q < 8; ++q)
        #pragma unroll
        for (int bi = 0; bi < 4; ++bi) acc[q][bi] = 0ull;

    #pragma unroll 8
    for (int k = 0; k < DIM; ++k) {
        ulonglong2 B0 = *(const ulonglong2*)&xb_s[k * JT + lane * 4];
        ulonglong2 B1 = *(const ulonglong2*)&xb_s[k * JT + lane * 4 + 128];
        #pragma unroll
        for (int q = 0; q < 8; ++q) {
            float xv = __shfl_sync(0xffffffffu, xr[q], k);
            unsigned long long xq2;
            PACK2(xq2, xv, xv);
            FMA2(acc[q][0], xq2, B0.x, acc[q][0]);
            FMA2(acc[q][1], xq2, B0.y, acc[q][1]);
            FMA2(acc[q][2], xq2, B1.x, acc[q][2]);
            FMA2(acc[q][3], xq2, B1.y, acc[q][3]);
        }
    }

    CP_WAIT(0);          // r tile arrived
    __syncthreads();     // also publishes b2_s

    // -------- epilogue: dist, exp, accumulate (all smem) --------
    const float L2E = 1.4426950408889634f;
    const float crf = r_scale[0] * L2E;
    const float cdf = -L2E / sigma[0];
    unsigned long long cr2, cd2, n22;
    PACK2(cr2, crf, crf);
    PACK2(cd2, cdf, cdf);
    PACK2(n22, -2.0f, -2.0f);

    #pragma unroll
    for (int q = 0; q < 8; ++q) {
        const int qg = qg0 + q;
        unsigned long long q2d;
        PACK2(q2d, q2w[q], q2w[q]);
        const float* rrow = r_s + (warp * 8 + q) * JT;
        unsigned long long kt = 0ull, kyt = 0ull;

        #pragma unroll
        for (int h = 0; h < 2; ++h) {
            const int joff = lane * 4 + 128 * h;
            ulonglong2 rv = *(const ulonglong2*)&rrow[joff];
            ulonglong2 bb = *(const ulonglong2*)&b2_s[joff];
            ulonglong2 yy = *(const ulonglong2*)&y_s[joff];
            #pragma unroll
            for (int p = 0; p < 2; ++p) {
                unsigned long long a  = acc[q][h * 2 + p];
                unsigned long long bp = p ? bb.y : bb.x;
                unsigned long long yp = p ? yy.y : yy.x;
                unsigned long long rp = p ? rv.y : rv.x;
                unsigned long long s2, d22, dd, rc, tt, kk;
                ADD2(s2, q2d, bp);
                FMA2(d22, a, n22, s2);              // d2 = q2 + b2 - 2*dot
                float dl, dh;
                UNPACK2(dl, dh, d22);
                dl = fmaxf(dl, 0.f);
                dh = fmaxf(dh, 0.f);
                SQRTA(dl, dl);
                SQRTA(dh, dh);
                PACK2(dd, dl, dh);
                MUL2(rc, rp, cr2);                   // r * (r_scale*log2e)
                FMA2(tt, dd, cd2, rc);               // -dist*(log2e/sigma) + ...
                float tl, th, kl, kh;
                UNPACK2(tl, th, tt);
                EX2A(kl, tl);
                EX2A(kh, th);
                PACK2(kk, kl, kh);
                ADD2(kt, kt, kk);
                FMA2(kyt, kk, yp, kyt);
            }
        }

        float a0, a1, ks, ky;
        UNPACK2(a0, a1, kt);
        ks = a0 + a1;
        UNPACK2(a0, a1, kyt);
        ky = a0 + a1;
        #pragma unroll
        for (int off = 16; off; off >>= 1) {
            ks += __shfl_xor_sync(0xffffffffu, ks, off);
            ky += __shfl_xor_sync(0xffffffffu, ky, off);
        }
        if (lane == 0) {
            g_part[(qg * JSPLIT + blockIdx.y) * 2 + 0] = ks;
            g_part[(qg * JSPLIT + blockIdx.y) * 2 + 1] = ky;
        }
    }
}

// ---------------- final reduce over j-splits (deterministic) ----------------
__global__ void nw_reduce(float* __restrict__ out) {
    int q = blockIdx.x * blockDim.x + threadIdx.x;
    if (q < NQ) {
        float ks = 0.f, ky = 0.f;
        const float2* p = (const float2*)&g_part[q * JSPLIT * 2];
        #pragma unroll
        for (int s = 0; s < JSPLIT; ++s) {
            float2 v = p[s];
            ks += v.x;
            ky += v.y;
        }
        out[q] = ky / (ks + 1e-8f);
    }
}

// ---------------- launch ----------------
extern "C" void kernel_launch(void* const* d_in, const int* in_sizes, int n_in,
                              void* d_out, int out_size) {
    (void)in_sizes; (void)n_in; (void)out_size;
    const float* x_backgnd = (const float*)d_in[0];
    const float* y_backgnd = (const float*)d_in[1];
    const float* x_query   = (const float*)d_in[2];
    const float* r         = (const float*)d_in[3];
    const float* sigma     = (const float*)d_in[4];
    const float* r_scale   = (const float*)d_in[5];
    const float* w         = (const float*)d_in[6];
    float* out = (float*)d_out;

    const int smem_bytes = (DIM * JT + QT * JT + 2 * JT) * 4;   // ~98 KB
    cudaFuncSetAttribute(nw_main, cudaFuncAttributeMaxDynamicSharedMemorySize, smem_bytes);

    prep<<<(NB * 8 + NQ * 8 + 255) / 256, 256>>>(x_backgnd, x_query, w);
    nw_main<<<dim3(NQ / QT, JSPLIT), 256, smem_bytes>>>(y_backgnd, r, sigma, r_scale);
    nw_reduce<<<(NQ + 255) / 256, 256>>>(out);
}

// round 6
// speedup vs baseline: 1.4656x; 1.2360x over previous
#include <cuda_runtime.h>
#include <cuda_bf16.h>
#include <cstdint>

#define NQ 2048
#define NB 8192
#define DIM 32
#define QTILE 128
#define JTILE 128
#define NQT (NQ / QTILE)   // 16
#define NJT (NB / JTILE)   // 64

// ---------------- device scratch (no allocs allowed) ----------------
__device__ float g_part[(size_t)NQ * NJT * 2];   // [q][jt]{ksum, kysum}

// ---------------- smem layout (bytes) ----------------
// A/B tiles: row-per-point, 144-B stride (64 bf16 = hi[32] | lo[32] = 128 B + 16 pad)
// -> ldmatrix row addresses land on distinct bank groups (36 banks/row => 4*row mod 32).
#define ROWB 144
#define SRSTRIDE 528                      // r tile row stride: 132 floats
#define SA 0
#define SB (SA + QTILE * ROWB)            // 18432
#define SR (SB + JTILE * ROWB)            // 36864
#define SY (SR + QTILE * SRSTRIDE)       // 104448
#define SQ2 (SY + 512)                    // 104960
#define SB2 (SQ2 + 512)                   // 105472
#define SPART (SB2 + 512)                 // 105984
#define SM_SIZE (SPART + 2048)            // 108032

// ---------------- asm helpers ----------------
#define SQRTA(d, x)  asm("sqrt.approx.ftz.f32 %0, %1;" : "=f"(d) : "f"(x))
#define EX2A(d, x)   asm("ex2.approx.ftz.f32 %0, %1;"  : "=f"(d) : "f"(x))
#define CP16(dst, src) asm volatile("cp.async.cg.shared.global [%0], [%1], 16;" :: "r"(dst), "l"(src))
#define CP_COMMIT()  asm volatile("cp.async.commit_group;")
#define CP_WAIT0()   asm volatile("cp.async.wait_group 0;")

__device__ __forceinline__ uint32_t smem_u32(const void* p) {
    uint32_t a;
    asm("{ .reg .u64 t; cvta.to.shared.u64 t, %1; cvt.u32.u64 %0, t; }" : "=r"(a) : "l"(p));
    return a;
}

#define LDSM_X4(r0, r1, r2, r3, addr)                                              \
    asm volatile("ldmatrix.sync.aligned.m8n8.x4.shared.b16 {%0,%1,%2,%3}, [%4];"   \
        : "=r"(r0), "=r"(r1), "=r"(r2), "=r"(r3) : "r"(addr))

#define MMA16816(d, a, b0, b1)                                                     \
    asm volatile("mma.sync.aligned.m16n8k16.row.col.f32.bf16.bf16.f32 "            \
        "{%0,%1,%2,%3}, {%4,%5,%6,%7}, {%8,%9}, {%0,%1,%2,%3};"                    \
        : "+f"((d)[0]), "+f"((d)[1]), "+f"((d)[2]), "+f"((d)[3])                   \
        : "r"((a)[0]), "r"((a)[1]), "r"((a)[2]), "r"((a)[3]), "r"(b0), "r"(b1))

// weighted hi/lo bf16 split of 16 coords -> smem row (hi at +0, lo at +64), + sumsq
__device__ __forceinline__ float split16(const float* __restrict__ src,
                                         const float* __restrict__ wv,
                                         char* dst) {
    float x[16];
    #pragma unroll
    for (int i = 0; i < 4; ++i) {
        float4 v = *(const float4*)&src[i * 4];
        x[i*4+0] = v.x * wv[i*4+0]; x[i*4+1] = v.y * wv[i*4+1];
        x[i*4+2] = v.z * wv[i*4+2]; x[i*4+3] = v.w * wv[i*4+3];
    }
    float s = 0.f;
    uint32_t h32[8], l32[8];
    #pragma unroll
    for (int i = 0; i < 8; ++i) {
        float x0 = x[2*i], x1 = x[2*i+1];
        __nv_bfloat16 h0 = __float2bfloat16(x0);
        __nv_bfloat16 h1 = __float2bfloat16(x1);
        float r0 = x0 - __bfloat162float(h0);
        float r1 = x1 - __bfloat162float(h1);
        __nv_bfloat162 hp = __halves2bfloat162(h0, h1);
        __nv_bfloat162 lp = __halves2bfloat162(__float2bfloat16(r0), __float2bfloat16(r1));
        h32[i] = *(uint32_t*)&hp;
        l32[i] = *(uint32_t*)&lp;
        s = fmaf(x0, x0, fmaf(x1, x1, s));
    }
    *(uint4*)(dst +  0) = make_uint4(h32[0], h32[1], h32[2], h32[3]);
    *(uint4*)(dst + 16) = make_uint4(h32[4], h32[5], h32[6], h32[7]);
    *(uint4*)(dst + 64) = make_uint4(l32[0], l32[1], l32[2], l32[3]);
    *(uint4*)(dst + 80) = make_uint4(l32[4], l32[5], l32[6], l32[7]);
    return s;
}

// ---------------- main: HMMA GEMM + fused epilogue ----------------
// grid (NQT=16, NJT=64), block 256 (8 warps, 2 CTAs/SM).
// warp = (wq 0..3) x (wj 0..1): 32q x 64j per warp; 2 m-tiles x 8 n-tiles of m16n8k16.
__global__ __launch_bounds__(256, 2) void nw_main(
    const float* __restrict__ xb,
    const float* __restrict__ xq,
    const float* __restrict__ w,
    const float* __restrict__ yb,
    const float* __restrict__ r,
    const float* __restrict__ sigma,
    const float* __restrict__ r_scale)
{
    extern __shared__ __align__(16) char smem_raw[];
    const uint32_t sbase = smem_u32(smem_raw);

    const int tid  = threadIdx.x;
    const int lane = tid & 31;
    const int warp = tid >> 5;
    const int wq   = warp >> 1;          // 0..3
    const int wj   = warp & 1;           // 0..1
    const int qt   = blockIdx.x;
    const int jt   = blockIdx.y;
    const int jb   = jt * JTILE;
    const int qb   = qt * QTILE;

    // ---- kick off the r tile + y stream first (cp.async, one group) ----
    #pragma unroll
    for (int i = 0; i < 16; ++i) {
        int e = tid + 256 * i;           // 4096 chunks of 16B
        int row = e >> 5;
        int c = e & 31;
        CP16(sbase + SR + row * SRSTRIDE + c * 16,
             (const char*)&r[(size_t)(qb + row) * NB + jb + c * 4]);
    }
    if (tid < 32)
        CP16(sbase + SY + tid * 16, (const char*)&yb[jb] + tid * 16);
    CP_COMMIT();

    // ---- in-block weighted hi/lo split of A (query) and B (backgnd) tiles ----
    {
        const int row = tid >> 1;
        const int hl  = tid & 1;
        float wv[16];
        #pragma unroll
        for (int i = 0; i < 4; ++i)
            *(float4*)&wv[i * 4] = *(const float4*)&w[hl * 16 + i * 4];

        float sA = split16(xq + (size_t)(qb + row) * DIM + hl * 16, wv,
                           smem_raw + SA + row * ROWB + hl * 32);
        float sB = split16(xb + (size_t)(jb + row) * DIM + hl * 16, wv,
                           smem_raw + SB + row * ROWB + hl * 32);
        sA += __shfl_xor_sync(0xffffffffu, sA, 1);
        sB += __shfl_xor_sync(0xffffffffu, sB, 1);
        if (hl == 0) {
            ((float*)(smem_raw + SQ2))[row] = sA;
            ((float*)(smem_raw + SB2))[row] = sB;
        }
    }

    const float L2E = 1.4426950408889634f;
    const float crf = r_scale[0] * L2E;
    const float cdf = -L2E / sigma[0];

    __syncthreads();   // A/B/q2/b2 tiles ready

    // ---- HMMA phase: D = Ahi.Bhi + Ahi.Blo + Alo.Bhi over K=32 ----
    float d[2][8][4];
    #pragma unroll
    for (int mt = 0; mt < 2; ++mt)
        #pragma unroll
        for (int nt = 0; nt < 8; ++nt)
            #pragma unroll
            for (int i = 0; i < 4; ++i) d[mt][nt][i] = 0.f;

    const uint32_t arow = sbase + SA + (uint32_t)(wq * 32 + (lane & 15)) * ROWB
                        + ((lane >> 4) & 1) * 16;
    const uint32_t brow = sbase + SB
                        + (uint32_t)(wj * 64 + ((lane >> 4) << 3) + (lane & 7)) * ROWB
                        + ((lane >> 3) & 1) * 16;

    const int AOFF[6] = { 0, 32, 0, 32, 64, 96 };    // hi0 hi1 hi0 hi1 lo0 lo1
    const int BOFF[6] = { 0, 32, 64, 96, 0, 32 };    // hi0 hi1 lo0 lo1 hi0 hi1

    #pragma unroll
    for (int c = 0; c < 6; ++c) {
        uint32_t a[2][4], b[4][4];
        LDSM_X4(a[0][0], a[0][1], a[0][2], a[0][3], arow + AOFF[c]);
        LDSM_X4(a[1][0], a[1][1], a[1][2], a[1][3], arow + 16 * ROWB + AOFF[c]);
        #pragma unroll
        for (int p = 0; p < 4; ++p)
            LDSM_X4(b[p][0], b[p][1], b[p][2], b[p][3], brow + p * 16 * ROWB + BOFF[c]);
        #pragma unroll
        for (int mt = 0; mt < 2; ++mt)
            #pragma unroll
            for (int nt = 0; nt < 8; ++nt)
                MMA16816(d[mt][nt], a[mt], b[nt >> 1][(nt & 1) * 2], b[nt >> 1][(nt & 1) * 2 + 1]);
    }

    CP_WAIT0();        // r + y arrived
    __syncthreads();

    // ---- epilogue: dist, exp, accumulate (all smem) ----
    const int g = lane >> 2;
    const int t = lane & 3;

    float q2r[4];
    #pragma unroll
    for (int mt = 0; mt < 2; ++mt)
        #pragma unroll
        for (int h = 0; h < 2; ++h)
            q2r[mt * 2 + h] = ((const float*)(smem_raw + SQ2))[wq * 32 + mt * 16 + g + 8 * h];

    float ks[4] = {0.f, 0.f, 0.f, 0.f}, ky[4] = {0.f, 0.f, 0.f, 0.f};

    #pragma unroll
    for (int nt = 0; nt < 8; ++nt) {
        const int jo = wj * 64 + nt * 8 + 2 * t;
        float2 b2p = *(const float2*)(smem_raw + SB2 + jo * 4);
        float2 yp  = *(const float2*)(smem_raw + SY  + jo * 4);
        #pragma unroll
        for (int mt = 0; mt < 2; ++mt) {
            #pragma unroll
            for (int h = 0; h < 2; ++h) {
                const int idx = mt * 2 + h;
                const int qr = wq * 32 + mt * 16 + g + 8 * h;
                float2 rv = *(const float2*)(smem_raw + SR + qr * SRSTRIDE + jo * 4);
                float dot0 = d[mt][nt][h * 2 + 0];
                float dot1 = d[mt][nt][h * 2 + 1];
                float base = q2r[idx];

                float d20 = fmaf(-2.f, dot0, base + b2p.x);
                float d21 = fmaf(-2.f, dot1, base + b2p.y);
                d20 = fmaxf(d20, 0.f);
                d21 = fmaxf(d21, 0.f);
                float ds0, ds1;
                SQRTA(ds0, d20);
                SQRTA(ds1, d21);
                float lg0 = fmaf(cdf, ds0, crf * rv.x);
                float lg1 = fmaf(cdf, ds1, crf * rv.y);
                float k0, k1;
                EX2A(k0, lg0);
                EX2A(k1, lg1);
                ks[idx] += k0 + k1;
                ky[idx] = fmaf(k0, yp.x, fmaf(k1, yp.y, ky[idx]));
            }
        }
    }

    // reduce across the 4 t-lanes of each g-group; one owner per (qr, wj)
    #pragma unroll
    for (int idx = 0; idx < 4; ++idx) {
        float a = ks[idx], b = ky[idx];
        a += __shfl_xor_sync(0xffffffffu, a, 1);
        b += __shfl_xor_sync(0xffffffffu, b, 1);
        a += __shfl_xor_sync(0xffffffffu, a, 2);
        b += __shfl_xor_sync(0xffffffffu, b, 2);
        if (t == 0) {
            const int mt = idx >> 1, h = idx & 1;
            const int qr = wq * 32 + mt * 16 + g + 8 * h;
            *(float2*)(smem_raw + SPART + (qr * 2 + wj) * 8) = make_float2(a, b);
        }
    }
    __syncthreads();

    if (tid < 128) {
        float2 a = *(const float2*)(smem_raw + SPART + (tid * 2 + 0) * 8);
        float2 b = *(const float2*)(smem_raw + SPART + (tid * 2 + 1) * 8);
        *(float2*)&g_part[((size_t)(qb + tid) * NJT + jt) * 2] =
            make_float2(a.x + b.x, a.y + b.y);
    }
}

// ---------------- final reduce over j-tiles (deterministic) ----------------
__global__ void nw_reduce(float* __restrict__ out) {
    int tId = blockIdx.x * 256 + threadIdx.x;    // 4096 threads: (q, half)
    int q = tId >> 1, h = tId & 1;
    const float2* p = (const float2*)&g_part[(size_t)q * NJT * 2] + h * 32;
    float ks = 0.f, ky = 0.f;
    #pragma unroll
    for (int s = 0; s < 32; ++s) {
        float2 v = p[s];
        ks += v.x;
        ky += v.y;
    }
    ks += __shfl_xor_sync(0xffffffffu, ks, 1);
    ky += __shfl_xor_sync(0xffffffffu, ky, 1);
    if (h == 0) out[q] = ky / (ks + 1e-8f);
}

// ---------------- launch ----------------
extern "C" void kernel_launch(void* const* d_in, const int* in_sizes, int n_in,
                              void* d_out, int out_size) {
    (void)in_sizes; (void)n_in; (void)out_size;
    const float* x_backgnd = (const float*)d_in[0];
    const float* y_backgnd = (const float*)d_in[1];
    const float* x_query   = (const float*)d_in[2];
    const float* r         = (const float*)d_in[3];
    const float* sigma     = (const float*)d_in[4];
    const float* r_scale   = (const float*)d_in[5];
    const float* w         = (const float*)d_in[6];
    float* out = (float*)d_out;

    cudaFuncSetAttribute(nw_main, cudaFuncAttributeMaxDynamicSharedMemorySize, SM_SIZE);

    nw_main<<<dim3(NQT, NJT), 256, SM_SIZE>>>(x_backgnd, x_query, w,
                                              y_backgnd, r, sigma, r_scale);
    nw_reduce<<<(NQ * 2) / 256, 256>>>(out);
}